// round 1
// baseline (speedup 1.0000x reference)
#include <cuda_runtime.h>

#define TTOK 3136
#define DM 512

// Scratch (device globals — no allocation allowed)
__device__ float g_q[TTOK * DM];
__device__ float g_k[TTOK * DM];
__device__ float g_v[TTOK * DM];
__device__ float g_ao[TTOK * DM];

// ---------------------------------------------------------------------------
// GEMM: out[M=3136, N=512] = (A1 (+A2)) @ W[512,512] + bias
// Tiles: BM=64, BN=64, BK=16; 256 threads; 4x4 microtile per thread.
// ---------------------------------------------------------------------------
__global__ __launch_bounds__(256) void gemm512_kernel(
    const float* __restrict__ A1, const float* __restrict__ A2,
    const float* __restrict__ W, const float* __restrict__ bias,
    float* __restrict__ out)
{
    __shared__ float As[16][68];   // transposed A tile: As[k][m]
    __shared__ float Bs[16][68];

    const int tid = threadIdx.x;
    const int tx = tid & 15, ty = tid >> 4;
    const int m0 = blockIdx.y * 64;
    const int n0 = blockIdx.x * 64;

    // load indexing
    const int ar = tid >> 2,  ac4 = tid & 3;    // A tile: 64 rows x 4 float4
    const int br = tid >> 4,  bc4 = tid & 15;   // B tile: 16 rows x 16 float4

    float acc[4][4];
    #pragma unroll
    for (int i = 0; i < 4; i++)
        #pragma unroll
        for (int j = 0; j < 4; j++) acc[i][j] = 0.f;

    for (int k0 = 0; k0 < DM; k0 += 16) {
        float4 a = *(const float4*)(A1 + (size_t)(m0 + ar) * DM + k0 + ac4 * 4);
        if (A2) {
            float4 p2 = *(const float4*)(A2 + (size_t)(m0 + ar) * DM + k0 + ac4 * 4);
            a.x += p2.x; a.y += p2.y; a.z += p2.z; a.w += p2.w;
        }
        As[ac4 * 4 + 0][ar] = a.x;
        As[ac4 * 4 + 1][ar] = a.y;
        As[ac4 * 4 + 2][ar] = a.z;
        As[ac4 * 4 + 3][ar] = a.w;

        float4 b = *(const float4*)(W + (size_t)(k0 + br) * DM + n0 + bc4 * 4);
        *(float4*)&Bs[br][bc4 * 4] = b;

        __syncthreads();
        #pragma unroll
        for (int kk = 0; kk < 16; kk++) {
            float4 av = *(float4*)&As[kk][ty * 4];
            float4 bv = *(float4*)&Bs[kk][tx * 4];
            float aa[4] = {av.x, av.y, av.z, av.w};
            float bb[4] = {bv.x, bv.y, bv.z, bv.w};
            #pragma unroll
            for (int i = 0; i < 4; i++)
                #pragma unroll
                for (int j = 0; j < 4; j++)
                    acc[i][j] += aa[i] * bb[j];
        }
        __syncthreads();
    }

    #pragma unroll
    for (int i = 0; i < 4; i++) {
        int m = m0 + ty * 4 + i;
        #pragma unroll
        for (int j = 0; j < 4; j++) {
            int n = n0 + tx * 4 + j;
            out[(size_t)m * DM + n] = acc[i][j] + bias[n];
        }
    }
}

// ---------------------------------------------------------------------------
// Block-diagonal flash attention.
// Grid: (T/56, H). Block: 224 threads = 56 rows x 4 subs (16 dims each).
// Online softmax; per-row segment masking (robust even if a tile straddled).
// ---------------------------------------------------------------------------
#define QS_STRIDE 68
#define PS_STRIDE 57
#define ATTN_SMEM_FLOATS (3 * 56 * QS_STRIDE + 56 * PS_STRIDE)

__global__ __launch_bounds__(224) void attn_kernel(
    const float* __restrict__ gq, const float* __restrict__ gk,
    const float* __restrict__ gv, const int* __restrict__ channels,
    float* __restrict__ gout)
{
    extern __shared__ float sm[];
    float* Qs = sm;                        // [56][68]
    float* Ks = Qs + 56 * QS_STRIDE;       // [56][68]
    float* Vs = Ks + 56 * QS_STRIDE;       // [56][68]
    float* Ps = Vs + 56 * QS_STRIDE;       // [56][57]

    const int h   = blockIdx.y;
    const int q0  = blockIdx.x * 56;
    const int tid = threadIdx.x;
    const int row = tid >> 2;
    const int sub = tid & 3;

    // Segment boundaries from channels (4 entries, seg i has channels[i]*196 tokens)
    int bnd1 = channels[0] * 196;
    int bnd2 = bnd1 + channels[1] * 196;
    int bnd3 = bnd2 + channels[2] * 196;
    int bnd4 = bnd3 + channels[3] * 196;

    int my_t = q0 + row;
    int my_s, my_e;
    if      (my_t < bnd1) { my_s = 0;    my_e = bnd1; }
    else if (my_t < bnd2) { my_s = bnd1; my_e = bnd2; }
    else if (my_t < bnd3) { my_s = bnd2; my_e = bnd3; }
    else                  { my_s = bnd3; my_e = bnd4; }

    // Block-wide kv range: from segment of first row to end of segment of last row
    int t0 = q0, t1 = q0 + 55;
    int blk_s, blk_e;
    if      (t0 < bnd1) blk_s = 0;
    else if (t0 < bnd2) blk_s = bnd1;
    else if (t0 < bnd3) blk_s = bnd2;
    else                blk_s = bnd3;
    if      (t1 < bnd1) blk_e = bnd1;
    else if (t1 < bnd2) blk_e = bnd2;
    else if (t1 < bnd3) blk_e = bnd3;
    else                blk_e = bnd4;

    // Load Q tile: 56 rows x 64 dims of head h
    for (int i = tid; i < 56 * 16; i += 224) {
        int r = i >> 4, c = i & 15;
        float4 v = *(const float4*)(gq + (size_t)(q0 + r) * DM + h * 64 + c * 4);
        *(float4*)&Qs[r * QS_STRIDE + c * 4] = v;
    }

    float o[16];
    #pragma unroll
    for (int d = 0; d < 16; d++) o[d] = 0.f;
    float m_i = -1e30f, l_i = 0.f;

    for (int kv = blk_s; kv < blk_e; kv += 56) {
        __syncthreads();
        for (int i = tid; i < 56 * 16; i += 224) {
            int r = i >> 4, c = i & 15;
            int kr = kv + r;
            float4 kx = make_float4(0.f, 0.f, 0.f, 0.f);
            float4 vx = make_float4(0.f, 0.f, 0.f, 0.f);
            if (kr < TTOK) {
                kx = *(const float4*)(gk + (size_t)kr * DM + h * 64 + c * 4);
                vx = *(const float4*)(gv + (size_t)kr * DM + h * 64 + c * 4);
            }
            *(float4*)&Ks[r * QS_STRIDE + c * 4] = kx;
            *(float4*)&Vs[r * QS_STRIDE + c * 4] = vx;
        }
        __syncthreads();

        // Scores: each thread handles keys [sub*14, sub*14+14)
        float s_[14];
        #pragma unroll
        for (int kk = 0; kk < 14; kk++) s_[kk] = 0.f;
        #pragma unroll
        for (int d4 = 0; d4 < 16; d4++) {
            float4 q4 = *(float4*)&Qs[row * QS_STRIDE + d4 * 4];
            #pragma unroll
            for (int kk = 0; kk < 14; kk++) {
                float4 k4 = *(float4*)&Ks[(sub * 14 + kk) * QS_STRIDE + d4 * 4];
                s_[kk] += q4.x * k4.x + q4.y * k4.y + q4.z * k4.z + q4.w * k4.w;
            }
        }

        bool valid[14];
        float mloc = -1e30f;
        #pragma unroll
        for (int kk = 0; kk < 14; kk++) {
            int kg = kv + sub * 14 + kk;
            valid[kk] = (kg >= my_s && kg < my_e);
            s_[kk] = valid[kk] ? s_[kk] * 0.125f : -1e30f;
            mloc = fmaxf(mloc, s_[kk]);
        }
        // row-max across the 4 subs of this row (consecutive lanes)
        mloc = fmaxf(mloc, __shfl_xor_sync(0xffffffffu, mloc, 1));
        mloc = fmaxf(mloc, __shfl_xor_sync(0xffffffffu, mloc, 2));
        float m_new = fmaxf(m_i, mloc);
        float alpha = __expf(m_i - m_new);

        float lloc = 0.f;
        #pragma unroll
        for (int kk = 0; kk < 14; kk++) {
            float p = valid[kk] ? __expf(s_[kk] - m_new) : 0.f;
            Ps[row * PS_STRIDE + sub * 14 + kk] = p;
            lloc += p;
        }
        lloc += __shfl_xor_sync(0xffffffffu, lloc, 1);
        lloc += __shfl_xor_sync(0xffffffffu, lloc, 2);
        l_i = l_i * alpha + lloc;

        #pragma unroll
        for (int d = 0; d < 16; d++) o[d] *= alpha;
        __syncwarp();   // Ps writes visible to the other subs of this row

        #pragma unroll
        for (int k = 0; k < 56; k++) {
            float p = Ps[row * PS_STRIDE + k];
            float4 v0 = *(float4*)&Vs[k * QS_STRIDE + sub * 16 + 0];
            float4 v1 = *(float4*)&Vs[k * QS_STRIDE + sub * 16 + 4];
            float4 v2 = *(float4*)&Vs[k * QS_STRIDE + sub * 16 + 8];
            float4 v3 = *(float4*)&Vs[k * QS_STRIDE + sub * 16 + 12];
            o[0]  += p * v0.x; o[1]  += p * v0.y; o[2]  += p * v0.z; o[3]  += p * v0.w;
            o[4]  += p * v1.x; o[5]  += p * v1.y; o[6]  += p * v1.z; o[7]  += p * v1.w;
            o[8]  += p * v2.x; o[9]  += p * v2.y; o[10] += p * v2.z; o[11] += p * v2.w;
            o[12] += p * v3.x; o[13] += p * v3.y; o[14] += p * v3.z; o[15] += p * v3.w;
        }
        m_i = m_new;
    }

    float inv = 1.f / l_i;
    #pragma unroll
    for (int d = 0; d < 16; d++)
        gout[(size_t)(q0 + row) * DM + h * 64 + sub * 16 + d] = o[d] * inv;
}

// ---------------------------------------------------------------------------
// Launch
// ---------------------------------------------------------------------------
extern "C" void kernel_launch(void* const* d_in, const int* in_sizes, int n_in,
                              void* d_out, int out_size)
{
    const float* xq  = (const float*)d_in[0];
    const float* xk  = (const float*)d_in[1];
    const float* pos = (const float*)d_in[2];
    const int*   ch  = (const int*)  d_in[3];
    const float* Wq  = (const float*)d_in[4];
    const float* bq  = (const float*)d_in[5];
    const float* Wk  = (const float*)d_in[6];
    const float* bk  = (const float*)d_in[7];
    const float* Wv  = (const float*)d_in[8];
    const float* bv  = (const float*)d_in[9];
    const float* Wo  = (const float*)d_in[10];
    const float* bo  = (const float*)d_in[11];
    float* out = (float*)d_out;

    float *q, *k, *v, *ao;
    cudaGetSymbolAddress((void**)&q,  g_q);
    cudaGetSymbolAddress((void**)&k,  g_k);
    cudaGetSymbolAddress((void**)&v,  g_v);
    cudaGetSymbolAddress((void**)&ao, g_ao);

    const size_t attn_smem = ATTN_SMEM_FLOATS * sizeof(float);
    cudaFuncSetAttribute(attn_kernel, cudaFuncAttributeMaxDynamicSharedMemorySize,
                         (int)attn_smem);

    dim3 gg(DM / 64, TTOK / 64);   // (8, 49)

    gemm512_kernel<<<gg, 256>>>(xq, pos, Wq, bq, q);
    gemm512_kernel<<<gg, 256>>>(xk, pos, Wk, bk, k);
    gemm512_kernel<<<gg, 256>>>(xk, nullptr, Wv, bv, v);
    attn_kernel<<<dim3(TTOK / 56, 8), 224, attn_smem>>>(q, k, v, ch, ao);
    gemm512_kernel<<<gg, 256>>>(ao, nullptr, Wo, bo, out);
}